// round 3
// baseline (speedup 1.0000x reference)
#include <cuda_runtime.h>
#include <cuda_bf16.h>
#include <math.h>

// ---------------- problem constants ----------------
#define Nn     46080      // total nodes (512*90)
#define Ee     737280     // edges (Nn*16)
#define Hh     128        // hidden
#define Bb     512        // graphs
#define NODESC 90
#define F_IN   90
#define HLc    64

// ---------------- device scratch (no allocations allowed) ----------------
__device__ float g_deg[Nn];
__device__ float g_dis[Nn];
__device__ int   g_cnt[Nn];
__device__ int   g_rowptr[Nn + 1];
__device__ int   g_cursor[Nn];
__device__ int   g_col[Ee];
__device__ float g_val[Ee];
__device__ float g_hw[Nn * Hh];
__device__ float g_h1[Nn * Hh];
__device__ float g_h2[Nn * Hh];
__device__ float g_h3[Nn * Hh];
__device__ float g_lin1[Bb * HLc];

// ---------------- 1) init ----------------
__global__ void init_kernel() {
    int i = blockIdx.x * blockDim.x + threadIdx.x;
    if (i < Nn) { g_deg[i] = 1.0f; g_cnt[i] = 0; }      // self-loop weight 1
    if (i < Bb * HLc) g_lin1[i] = 0.0f;
}

// ---------------- 2) degree + in-edge counts (edge_index is INT32) ----------------
__global__ void count_kernel(const int* __restrict__ ei,
                             const float* __restrict__ ea) {
    int e = blockIdx.x * blockDim.x + threadIdx.x;
    if (e >= Ee) return;
    int d = ei[Ee + e];
    atomicAdd(&g_deg[d], ea[e]);
    atomicAdd(&g_cnt[d], 1);
}

// ---------------- 3) dis = rsqrt(deg) ----------------
__global__ void dis_kernel() {
    int i = blockIdx.x * blockDim.x + threadIdx.x;
    if (i < Nn) g_dis[i] = rsqrtf(g_deg[i]);
}

// ---------------- 4) exclusive scan of counts -> rowptr (1 block) ----------------
__global__ void scan_kernel() {
    __shared__ int ssum[1024];
    const int CH = Nn / 1024;  // 45 exactly
    int t = threadIdx.x;
    int base = t * CH;
    int s = 0;
    for (int i = 0; i < CH; i++) s += g_cnt[base + i];
    ssum[t] = s;
    __syncthreads();
    for (int off = 1; off < 1024; off <<= 1) {
        int v = (t >= off) ? ssum[t - off] : 0;
        __syncthreads();
        ssum[t] += v;
        __syncthreads();
    }
    int run = (t == 0) ? 0 : ssum[t - 1];
    for (int i = 0; i < CH; i++) {
        int idx = base + i;
        g_rowptr[idx] = run;
        g_cursor[idx] = run;
        run += g_cnt[idx];
    }
    if (t == 1023) g_rowptr[Nn] = Ee;
}

// ---------------- 5) CSR fill with precomputed per-edge norm ----------------
__global__ void fill_kernel(const int* __restrict__ ei,
                            const float* __restrict__ ea) {
    int e = blockIdx.x * blockDim.x + threadIdx.x;
    if (e >= Ee) return;
    int s = ei[e];
    int d = ei[Ee + e];
    int pos = atomicAdd(&g_cursor[d], 1);
    g_col[pos] = s;
    g_val[pos] = g_dis[s] * ea[e] * g_dis[d];
}

// ---------------- 6) GEMM: hW = h @ W  (h [Nn,Fin], W [Fin,128]) ----------------
// 128 threads per block, 32 rows per block, K chunked by 64.
__global__ void gemm_kernel(const float* __restrict__ hin,
                            const float* __restrict__ W,
                            float* __restrict__ out, int Fin) {
    __shared__ float Ws[64 * 128];   // 32 KB
    __shared__ float hs[32 * 64];    // 8 KB  [r][k]
    int tid = threadIdx.x;
    int row0 = blockIdx.x * 32;
    float acc[32];
#pragma unroll
    for (int r = 0; r < 32; r++) acc[r] = 0.0f;

    for (int k0 = 0; k0 < Fin; k0 += 64) {
        int kc = min(64, Fin - k0);
        for (int i = tid; i < 64 * 128; i += 128) {
            int k = i >> 7, c = i & 127;
            Ws[i] = (k < kc) ? W[(k0 + k) * Hh + c] : 0.0f;
        }
        for (int i = tid; i < 32 * 64; i += 128) {
            int r = i >> 6, k = i & 63;
            hs[i] = (k < kc) ? hin[(row0 + r) * Fin + k0 + k] : 0.0f;
        }
        __syncthreads();
        int kcr = (kc + 3) & ~3;
        for (int k = 0; k < kcr; k += 4) {
            float w0 = Ws[(k + 0) * 128 + tid];
            float w1 = Ws[(k + 1) * 128 + tid];
            float w2 = Ws[(k + 2) * 128 + tid];
            float w3 = Ws[(k + 3) * 128 + tid];
#pragma unroll
            for (int r = 0; r < 32; r++) {
                float4 h4 = *(const float4*)&hs[r * 64 + k];
                acc[r] = fmaf(h4.x, w0, acc[r]);
                acc[r] = fmaf(h4.y, w1, acc[r]);
                acc[r] = fmaf(h4.z, w2, acc[r]);
                acc[r] = fmaf(h4.w, w3, acc[r]);
            }
        }
        __syncthreads();
    }
#pragma unroll
    for (int r = 0; r < 32; r++) out[(row0 + r) * Hh + tid] = acc[r];
}

// ---------------- 7) aggregate: out = relu(segsum(norm*hW[src]) + self + b) ----------------
__global__ void agg_kernel(const float* __restrict__ hw,
                           const float* __restrict__ b,
                           float* __restrict__ hout) {
    int node = blockIdx.x * 8 + (threadIdx.x >> 5);
    int lane = threadIdx.x & 31;
    float sn = g_dis[node];
    sn = sn * sn;  // self-loop norm
    float4 acc = *(const float4*)(hw + node * Hh + lane * 4);
    acc.x *= sn; acc.y *= sn; acc.z *= sn; acc.w *= sn;
    int beg = g_rowptr[node], end = g_rowptr[node + 1];
    for (int e = beg; e < end; e++) {
        int s = g_col[e];
        float nv = g_val[e];
        float4 v = *(const float4*)(hw + s * Hh + lane * 4);
        acc.x = fmaf(nv, v.x, acc.x);
        acc.y = fmaf(nv, v.y, acc.y);
        acc.z = fmaf(nv, v.z, acc.z);
        acc.w = fmaf(nv, v.w, acc.w);
    }
    float4 bb = ((const float4*)b)[lane];
    acc.x = fmaxf(acc.x + bb.x, 0.0f);
    acc.y = fmaxf(acc.y + bb.y, 0.0f);
    acc.z = fmaxf(acc.z + bb.z, 0.0f);
    acc.w = fmaxf(acc.w + bb.w, 0.0f);
    *(float4*)(hout + node * Hh + lane * 4) = acc;
}

// ---------------- 8) lin1: [512, 34560] @ [34560, 64], split-K + graph-tiled ----------------
__global__ void lin1_kernel(const float* __restrict__ W) {
    __shared__ float zs[16 * 384];  // 24 KB
    int col = threadIdx.x & 63;
    int kl  = threadIdx.x >> 6;     // 0..3
    int g0 = blockIdx.y * 16;
    int kbase = blockIdx.x * 1920;
    float acc[16];
#pragma unroll
    for (int g = 0; g < 16; g++) acc[g] = 0.0f;

    for (int nb = 0; nb < 5; nb++) {
        int kb = kbase + nb * 384;
        int node = kb / 384;
        for (int i = threadIdx.x; i < 16 * 384; i += 256) {
            int g = i / 384;
            int r = i % 384;
            int layer = r >> 7, feat = r & 127;
            const float* hp = (layer == 0) ? g_h1 : (layer == 1) ? g_h2 : g_h3;
            zs[i] = hp[((g0 + g) * NODESC + node) * Hh + feat];
        }
        __syncthreads();
        int kbeg = kl * 96, kend = kbeg + 96;
        for (int k = kbeg; k < kend; k += 4) {
            long kg = (long)(kb + k);
            float w0 = W[(kg + 0) * HLc + col];
            float w1 = W[(kg + 1) * HLc + col];
            float w2 = W[(kg + 2) * HLc + col];
            float w3 = W[(kg + 3) * HLc + col];
#pragma unroll
            for (int g = 0; g < 16; g++) {
                float4 z4 = *(const float4*)&zs[g * 384 + k];
                acc[g] = fmaf(z4.x, w0, acc[g]);
                acc[g] = fmaf(z4.y, w1, acc[g]);
                acc[g] = fmaf(z4.z, w2, acc[g]);
                acc[g] = fmaf(z4.w, w3, acc[g]);
            }
        }
        __syncthreads();
    }
#pragma unroll
    for (int g = 0; g < 16; g++)
        atomicAdd(&g_lin1[(g0 + g) * HLc + col], acc[g]);
}

// ---------------- 9) head: relu(+b) @ lin2 + log_softmax ----------------
__global__ void head_kernel(const float* __restrict__ lb,
                            const float* __restrict__ W2,
                            const float* __restrict__ b2,
                            float* __restrict__ out) {
    int g = blockIdx.x * blockDim.x + threadIdx.x;
    if (g >= Bb) return;
    float l0 = b2[0], l1 = b2[1];
    for (int j = 0; j < HLc; j++) {
        float h = fmaxf(g_lin1[g * HLc + j] + lb[j], 0.0f);
        l0 = fmaf(h, W2[j * 2 + 0], l0);
        l1 = fmaf(h, W2[j * 2 + 1], l1);
    }
    float m = fmaxf(l0, l1);
    float lse = m + logf(expf(l0 - m) + expf(l1 - m));
    out[g * 2 + 0] = l0 - lse;
    out[g * 2 + 1] = l1 - lse;
}

// ---------------- launch: inputs mapped BY SIZE (robust to metadata order) ----------------
extern "C" void kernel_launch(void* const* d_in, const int* in_sizes, int n_in,
                              void* d_out, int out_size) {
    const float *x = 0, *ea = 0, *W1 = 0, *W2 = 0, *W3 = 0;
    const float *b1 = 0, *b2 = 0, *b3 = 0, *l2W = 0;
    const float *l1W = 0, *l1b = 0, *l2b = 0;
    const int   *ei = 0;
    int n128 = 0, n16k = 0;

    for (int i = 0; i < n_in; i++) {
        const void* p = d_in[i];
        switch (in_sizes[i]) {
            case 4147200: x   = (const float*)p; break;            // x [46080,90]
            case 737280:  ea  = (const float*)p; break;            // edge_attr
            case 11520:   W1  = (const float*)p; break;            // W1 [90,128]
            case 16384:   if (n16k++ == 0) W2 = (const float*)p;   // W2 then W3
                          else             W3 = (const float*)p; break;
            case 128: {                                            // b1,b2,b3,lin2_W
                int k = n128++;
                if      (k == 0) b1  = (const float*)p;
                else if (k == 1) b2  = (const float*)p;
                else if (k == 2) b3  = (const float*)p;
                else             l2W = (const float*)p;
                break; }
            case 2211840: l1W = (const float*)p; break;            // lin1_W
            case 64:      l1b = (const float*)p; break;            // lin1_b
            case 2:       l2b = (const float*)p; break;            // lin2_b
            case 1474560: ei  = (const int*)p;   break;            // edge_index (int32!)
            default: break;                                        // batch (46080) unused
        }
    }
    float* out = (float*)d_out;

    float *hw, *h1, *h2, *h3;
    cudaGetSymbolAddress((void**)&hw, g_hw);
    cudaGetSymbolAddress((void**)&h1, g_h1);
    cudaGetSymbolAddress((void**)&h2, g_h2);
    cudaGetSymbolAddress((void**)&h3, g_h3);

    init_kernel<<<(Nn + 255) / 256, 256>>>();
    count_kernel<<<Ee / 256, 256>>>(ei, ea);
    dis_kernel<<<(Nn + 255) / 256, 256>>>();
    scan_kernel<<<1, 1024>>>();
    fill_kernel<<<Ee / 256, 256>>>(ei, ea);

    gemm_kernel<<<Nn / 32, 128>>>(x, W1, hw, F_IN);
    agg_kernel<<<Nn / 8, 256>>>(hw, b1, h1);
    gemm_kernel<<<Nn / 32, 128>>>(h1, W2, hw, Hh);
    agg_kernel<<<Nn / 8, 256>>>(hw, b2, h2);
    gemm_kernel<<<Nn / 32, 128>>>(h2, W3, hw, Hh);
    agg_kernel<<<Nn / 8, 256>>>(hw, b3, h3);

    lin1_kernel<<<dim3(18, 32), 256>>>(l1W);
    head_kernel<<<2, 256>>>(l1b, l2W, l2b, out);
}

// round 4
// speedup vs baseline: 1.1351x; 1.1351x over previous
#include <cuda_runtime.h>
#include <cuda_bf16.h>
#include <math.h>

// ---------------- problem constants ----------------
#define Nn     46080      // total nodes (512*90)
#define Ee     737280     // edges
#define Hh     128
#define Bb     512
#define NODESC 90
#define F_IN   90
#define HLc    64
#define CAP    64         // padded-CSR capacity per node

// ---------------- device scratch ----------------
__device__ float g_deg[Nn];
__device__ float g_dis[Nn];
__device__ int   g_cnt[Nn];
__device__ int   g_colp[(size_t)Nn * CAP];
__device__ float g_valp[(size_t)Nn * CAP];
__device__ float g_h1[Nn * Hh];
__device__ float g_h2[Nn * Hh];
__device__ float g_h3[Nn * Hh];
__device__ float g_lin1[Bb * HLc];

// ---------------- f32x2 packed helpers (Blackwell) ----------------
__device__ __forceinline__ unsigned long long pk2(float a, float b) {
    unsigned long long r;
    asm("mov.b64 %0,{%1,%2};" : "=l"(r) : "f"(a), "f"(b));
    return r;
}
__device__ __forceinline__ void upk2(unsigned long long v, float& a, float& b) {
    asm("mov.b64 {%0,%1},%2;" : "=f"(a), "=f"(b) : "l"(v));
}
__device__ __forceinline__ void fma2(unsigned long long& d,
                                     unsigned long long a,
                                     unsigned long long b) {
    asm("fma.rn.f32x2 %0,%1,%2,%0;" : "+l"(d) : "l"(a), "l"(b));
}

// ---------------- 1) init ----------------
__global__ void init_kernel() {
    int i = blockIdx.x * blockDim.x + threadIdx.x;
    if (i < Nn) { g_deg[i] = 1.0f; g_cnt[i] = 0; }   // self-loop weight 1
    if (i < Bb * HLc) g_lin1[i] = 0.0f;
}

// ---------------- 2) weighted in-degree ----------------
__global__ void count_kernel(const int* __restrict__ ei,
                             const float* __restrict__ ea) {
    int e = blockIdx.x * blockDim.x + threadIdx.x;
    if (e >= Ee) return;
    atomicAdd(&g_deg[ei[Ee + e]], ea[e]);
}

// ---------------- 3) dis = rsqrt(deg) ----------------
__global__ void dis_kernel() {
    int i = blockIdx.x * blockDim.x + threadIdx.x;
    if (i < Nn) g_dis[i] = rsqrtf(g_deg[i]);
}

// ---------------- 4) padded-CSR fill: val = dis[s]*w (dis[d] folded in agg) ----------------
__global__ void fill_kernel(const int* __restrict__ ei,
                            const float* __restrict__ ea) {
    int e = blockIdx.x * blockDim.x + threadIdx.x;
    if (e >= Ee) return;
    int s = ei[e];
    int d = ei[Ee + e];
    int slot = atomicAdd(&g_cnt[d], 1);
    if (slot < CAP) {
        size_t p = (size_t)d * CAP + slot;
        g_colp[p] = s % NODESC;           // local source index within graph
        g_valp[p] = g_dis[s] * ea[e];
    }
}

// ---------------- 5) fused conv: h_out = relu(A_hat @ (h_in @ W) + b) per graph ----------------
// One block = one graph. 256 threads = 128 cols x 2 row-halves.
// smem: hsT [FIN][100] (k-major row pairs), Ws [32][128] chunk, hw [90][128].
template <int FIN>
__global__ void conv_kernel(const float* __restrict__ hin,
                            const float* __restrict__ W,
                            const float* __restrict__ b,
                            float* __restrict__ hout) {
    extern __shared__ float sm[];
    float* hsT = sm;                          // FIN*100 floats
    float* Wsm = sm + FIN * 100;              // 4096 floats
    float* hw  = sm + FIN * 100 + 4096;       // 90*128 floats

    const int tid = threadIdx.x;
    const int g = blockIdx.x;
    const int gbase = g * NODESC;
    const float* hg = hin + (size_t)gbase * FIN;

    // stage hsT transposed: hsT[k*100 + r] = h[r][k], rows 90..95 zero
    for (int i = tid; i < 96 * FIN; i += 256) {
        int r = i / FIN, k = i - r * FIN;
        hsT[k * 100 + r] = (r < NODESC) ? hg[r * FIN + k] : 0.0f;
    }

    const int col = tid & 127;
    const int half = tid >> 7;
    unsigned long long acc[24];
#pragma unroll
    for (int p = 0; p < 24; p++) acc[p] = 0ull;

    for (int k0 = 0; k0 < FIN; k0 += 32) {
        __syncthreads();
        int kc = min(32, FIN - k0);
        for (int i = tid; i < kc * 128; i += 256)
            Wsm[i] = W[(k0 + (i >> 7)) * Hh + (i & 127)];
        __syncthreads();
        for (int kk = 0; kk < kc; kk++) {
            float w = Wsm[kk * 128 + col];
            unsigned long long wp = pk2(w, w);
            const ulonglong2* hp =
                (const ulonglong2*)&hsT[(k0 + kk) * 100 + half * 48];
#pragma unroll
            for (int q = 0; q < 12; q++) {
                ulonglong2 hh = hp[q];
                fma2(acc[2 * q], hh.x, wp);
                fma2(acc[2 * q + 1], hh.y, wp);
            }
        }
    }

    // write hw rows (skip padded rows >= 90)
#pragma unroll
    for (int q = 0; q < 12; q++) {
#pragma unroll
        for (int s2 = 0; s2 < 2; s2++) {
            float a, bv;
            upk2(acc[2 * q + s2], a, bv);
            int r0 = half * 48 + 4 * q + 2 * s2;
            if (r0 < NODESC)     hw[r0 * 128 + col] = a;
            if (r0 + 1 < NODESC) hw[(r0 + 1) * 128 + col] = bv;
        }
    }
    __syncthreads();

    // aggregate from smem: out = dd*(dd*hw[self] + sum val*hw[src]) + b, relu
    int grp = tid >> 5, lane = tid & 31;
    float4 bb = ((const float4*)b)[lane];
    for (int node = grp; node < NODESC; node += 8) {
        float dd = g_dis[gbase + node];
        int cn = g_cnt[gbase + node];
        if (cn > CAP) cn = CAP;
        const int*   cp = &g_colp[(size_t)(gbase + node) * CAP];
        const float* vp = &g_valp[(size_t)(gbase + node) * CAP];
        float4 acc4 = *(const float4*)&hw[node * 128 + lane * 4];
        acc4.x *= dd; acc4.y *= dd; acc4.z *= dd; acc4.w *= dd;
        for (int e = 0; e < cn; e++) {
            int sl = cp[e];
            float v = vp[e];
            float4 h4 = *(const float4*)&hw[sl * 128 + lane * 4];
            acc4.x = fmaf(v, h4.x, acc4.x);
            acc4.y = fmaf(v, h4.y, acc4.y);
            acc4.z = fmaf(v, h4.z, acc4.z);
            acc4.w = fmaf(v, h4.w, acc4.w);
        }
        float4 o;
        o.x = fmaxf(fmaf(dd, acc4.x, bb.x), 0.0f);
        o.y = fmaxf(fmaf(dd, acc4.y, bb.y), 0.0f);
        o.z = fmaxf(fmaf(dd, acc4.z, bb.z), 0.0f);
        o.w = fmaxf(fmaf(dd, acc4.w, bb.w), 0.0f);
        *(float4*)&hout[(size_t)(gbase + node) * 128 + lane * 4] = o;
    }
}

// ---------------- 6) lin1: [512,34560]@[34560,64] split-K, f32x2, graph pairs ----------------
__global__ void lin1_kernel(const float* __restrict__ W) {
    __shared__ float zs[384 * 20];  // zs[r*20+g], 16 graphs, stride 20
    int col = threadIdx.x & 63;
    int kl = threadIdx.x >> 6;      // 0..3
    int g0 = blockIdx.y * 16;
    int kbase = blockIdx.x * 1920;
    unsigned long long acc[8];
#pragma unroll
    for (int q = 0; q < 8; q++) acc[q] = 0ull;

    for (int nb = 0; nb < 5; nb++) {
        int kb = kbase + nb * 384;
        int node = kb / 384;
        __syncthreads();
        for (int i = threadIdx.x; i < 16 * 384; i += 256) {
            int g = i / 384, r = i - g * 384;
            int layer = r >> 7, feat = r & 127;
            const float* hp = (layer == 0) ? g_h1 : (layer == 1) ? g_h2 : g_h3;
            zs[r * 20 + g] = hp[((g0 + g) * NODESC + node) * Hh + feat];
        }
        __syncthreads();
        int kbeg = kl * 96;
#pragma unroll 4
        for (int k = kbeg; k < kbeg + 96; k++) {
            float w = __ldg(&W[(size_t)(kb + k) * HLc + col]);
            unsigned long long wp = pk2(w, w);
            const ulonglong2* zp = (const ulonglong2*)&zs[k * 20];
#pragma unroll
            for (int q = 0; q < 4; q++) {
                ulonglong2 zz = zp[q];
                fma2(acc[2 * q], zz.x, wp);
                fma2(acc[2 * q + 1], zz.y, wp);
            }
        }
    }
#pragma unroll
    for (int q = 0; q < 4; q++) {
#pragma unroll
        for (int s2 = 0; s2 < 2; s2++) {
            float a, bv;
            upk2(acc[2 * q + s2], a, bv);
            int gg = 4 * q + 2 * s2;
            atomicAdd(&g_lin1[(g0 + gg) * HLc + col], a);
            atomicAdd(&g_lin1[(g0 + gg + 1) * HLc + col], bv);
        }
    }
}

// ---------------- 7) head ----------------
__global__ void head_kernel(const float* __restrict__ lb,
                            const float* __restrict__ W2,
                            const float* __restrict__ b2,
                            float* __restrict__ out) {
    int g = blockIdx.x * blockDim.x + threadIdx.x;
    if (g >= Bb) return;
    float l0 = b2[0], l1 = b2[1];
    for (int j = 0; j < HLc; j++) {
        float h = fmaxf(g_lin1[g * HLc + j] + lb[j], 0.0f);
        l0 = fmaf(h, W2[j * 2 + 0], l0);
        l1 = fmaf(h, W2[j * 2 + 1], l1);
    }
    float m = fmaxf(l0, l1);
    float lse = m + logf(expf(l0 - m) + expf(l1 - m));
    out[g * 2 + 0] = l0 - lse;
    out[g * 2 + 1] = l1 - lse;
}

// ---------------- launch: inputs mapped BY SIZE ----------------
extern "C" void kernel_launch(void* const* d_in, const int* in_sizes, int n_in,
                              void* d_out, int out_size) {
    const float *x = 0, *ea = 0, *W1 = 0, *W2 = 0, *W3 = 0;
    const float *b1 = 0, *b2 = 0, *b3 = 0, *l2W = 0;
    const float *l1W = 0, *l1b = 0, *l2b = 0;
    const int *ei = 0;
    int n128 = 0, n16k = 0;

    for (int i = 0; i < n_in; i++) {
        const void* p = d_in[i];
        switch (in_sizes[i]) {
            case 4147200: x = (const float*)p; break;
            case 737280:  ea = (const float*)p; break;
            case 11520:   W1 = (const float*)p; break;
            case 16384:   if (n16k++ == 0) W2 = (const float*)p;
                          else             W3 = (const float*)p; break;
            case 128: {
                int k = n128++;
                if      (k == 0) b1 = (const float*)p;
                else if (k == 1) b2 = (const float*)p;
                else if (k == 2) b3 = (const float*)p;
                else             l2W = (const float*)p;
                break; }
            case 2211840: l1W = (const float*)p; break;
            case 64:      l1b = (const float*)p; break;
            case 2:       l2b = (const float*)p; break;
            case 1474560: ei = (const int*)p; break;
            default: break;  // batch unused
        }
    }
    float* out = (float*)d_out;

    float *h1, *h2, *h3;
    cudaGetSymbolAddress((void**)&h1, g_h1);
    cudaGetSymbolAddress((void**)&h2, g_h2);
    cudaGetSymbolAddress((void**)&h3, g_h3);

    const int smem90  = (F_IN * 100 + 4096 + NODESC * 128) * 4;  // 98464 B
    const int smem128 = (Hh  * 100 + 4096 + NODESC * 128) * 4;   // 113664 B
    cudaFuncSetAttribute(conv_kernel<F_IN>,
                         cudaFuncAttributeMaxDynamicSharedMemorySize, smem90);
    cudaFuncSetAttribute(conv_kernel<Hh>,
                         cudaFuncAttributeMaxDynamicSharedMemorySize, smem128);

    init_kernel<<<(Nn + 255) / 256, 256>>>();
    count_kernel<<<Ee / 256, 256>>>(ei, ea);
    dis_kernel<<<(Nn + 255) / 256, 256>>>();
    fill_kernel<<<Ee / 256, 256>>>(ei, ea);

    conv_kernel<F_IN><<<Bb, 256, smem90>>>(x, W1, b1, h1);
    conv_kernel<Hh><<<Bb, 256, smem128>>>(h1, W2, b2, h2);
    conv_kernel<Hh><<<Bb, 256, smem128>>>(h2, W3, b3, h3);

    lin1_kernel<<<dim3(18, 32), 256>>>(l1W);
    head_kernel<<<2, 256>>>(l1b, l2W, l2b, out);
}